// round 1
// baseline (speedup 1.0000x reference)
#include <cuda_runtime.h>
#include <math.h>

// Problem constants
#define B_   2
#define N_   2048
#define DIM  1024
#define H_   16
#define HD   64          // head dim
#define MN   (B_ * N_)   // 4096 total rows

// Scratch (device globals: allocation-free per harness rules)
__device__ float g_Q[(size_t)MN * DIM];
__device__ float g_K[(size_t)MN * DIM];
__device__ float g_V[(size_t)MN * DIM];
__device__ float g_O[(size_t)MN * DIM];

// ---------------------------------------------------------------------------
// SGEMM NT: C[M,N] = A[M,K] @ B[N,K]^T   (both row-major, K contiguous)
// 128x128x8 tile, 256 threads, 8x8 microtile.
// ---------------------------------------------------------------------------
__global__ __launch_bounds__(256) void sgemm_nt(
    const float* __restrict__ A, const float* __restrict__ B,
    float* __restrict__ C, int M, int N, int K)
{
    __shared__ float As[8][132];   // [k][m], pad 132 -> conflict-free transposed stores, 16B-aligned rows
    __shared__ float Bs[8][132];   // [k][n]

    const int tid = threadIdx.x;
    const int tx  = tid & 15;      // 0..15 -> 8 cols each
    const int ty  = tid >> 4;      // 0..15 -> 8 rows each
    const int m0  = blockIdx.y * 128;
    const int n0  = blockIdx.x * 128;

    // load mapping: each thread loads one float4 of A and B per k-step
    const int lr = tid >> 1;            // 0..127 row within tile
    const int lc = (tid & 1) * 4;       // 0 or 4 (col within 8-wide k slab)
    const float* Ap = A + (size_t)(m0 + lr) * K + lc;
    const float* Bp = B + (size_t)(n0 + lr) * K + lc;

    float acc[8][8];
    #pragma unroll
    for (int i = 0; i < 8; ++i)
        #pragma unroll
        for (int j = 0; j < 8; ++j) acc[i][j] = 0.f;

    for (int k0 = 0; k0 < K; k0 += 8) {
        float4 av = *(const float4*)(Ap + k0);
        float4 bv = *(const float4*)(Bp + k0);
        As[lc + 0][lr] = av.x; As[lc + 1][lr] = av.y;
        As[lc + 2][lr] = av.z; As[lc + 3][lr] = av.w;
        Bs[lc + 0][lr] = bv.x; Bs[lc + 1][lr] = bv.y;
        Bs[lc + 2][lr] = bv.z; Bs[lc + 3][lr] = bv.w;
        __syncthreads();

        #pragma unroll
        for (int kk = 0; kk < 8; ++kk) {
            float ra[8], rb[8];
            #pragma unroll
            for (int i = 0; i < 8; ++i) ra[i] = As[kk][ty * 8 + i];
            #pragma unroll
            for (int j = 0; j < 8; ++j) rb[j] = Bs[kk][tx * 8 + j];
            #pragma unroll
            for (int i = 0; i < 8; ++i)
                #pragma unroll
                for (int j = 0; j < 8; ++j)
                    acc[i][j] = fmaf(ra[i], rb[j], acc[i][j]);
        }
        __syncthreads();
    }

    #pragma unroll
    for (int i = 0; i < 8; ++i) {
        float* Cp = C + (size_t)(m0 + ty * 8 + i) * N + n0 + tx * 8;
        *(float4*)(Cp + 0) = make_float4(acc[i][0], acc[i][1], acc[i][2], acc[i][3]);
        *(float4*)(Cp + 4) = make_float4(acc[i][4], acc[i][5], acc[i][6], acc[i][7]);
    }
}

// ---------------------------------------------------------------------------
// Causal flash attention, fp32. One block = one (b,h, 64-row Q tile).
// Br = Bc = 64, d = 64. 256 threads, 4x4 microtiles for S and O.
// Online softmax; only lower-triangle KV tiles visited.
// ---------------------------------------------------------------------------
#define BR   64
#define BC   64
#define PADW 65
#define FLASH_SMEM ((size_t)(4 * BR * PADW) * sizeof(float))   // Qs,Ks,Vs,Ps

__global__ __launch_bounds__(256) void flash_causal(
    const float* __restrict__ Q, const float* __restrict__ K,
    const float* __restrict__ V, float* __restrict__ O)
{
    extern __shared__ float sm[];
    float* Qs = sm;                  // [64][65]
    float* Ks = Qs + BR * PADW;      // [64][65]
    float* Vs = Ks + BC * PADW;      // [64][65]
    float* Ps = Vs + BC * PADW;      // [64][65]

    const int it  = blockIdx.x;          // query tile
    const int bh  = blockIdx.y;          // b*H + h
    const int b   = bh >> 4;
    const int h   = bh & 15;
    const int tid = threadIdx.x;
    const int tx  = tid & 15;            // 4 cols each
    const int ty  = tid >> 4;            // 4 rows each
    const int i0  = it * BR;

    const float* Qb = Q + (size_t)b * N_ * DIM + h * HD;
    const float* Kb = K + (size_t)b * N_ * DIM + h * HD;
    const float* Vb = V + (size_t)b * N_ * DIM + h * HD;

    // load Q tile (natural layout, coalesced)
    for (int idx = tid; idx < BR * HD; idx += 256) {
        int r = idx >> 6, c = idx & 63;
        Qs[r * PADW + c] = Qb[(size_t)(i0 + r) * DIM + c];
    }

    float m_i[4], l_i[4], acc[4][4];
    #pragma unroll
    for (int i = 0; i < 4; ++i) {
        m_i[i] = -INFINITY; l_i[i] = 0.f;
        #pragma unroll
        for (int j = 0; j < 4; ++j) acc[i][j] = 0.f;
    }

    for (int jt = 0; jt <= it; ++jt) {
        const int j0 = jt * BC;
        __syncthreads();   // previous PV done; Qs visible on first iter
        for (int idx = tid; idx < BC * HD; idx += 256) {
            int r = idx >> 6, c = idx & 63;
            Ks[r * PADW + c] = Kb[(size_t)(j0 + r) * DIM + c];
            Vs[r * PADW + c] = Vb[(size_t)(j0 + r) * DIM + c];
        }
        __syncthreads();

        // S = Q K^T (4x4 per thread)
        float s[4][4];
        #pragma unroll
        for (int i = 0; i < 4; ++i)
            #pragma unroll
            for (int j = 0; j < 4; ++j) s[i][j] = 0.f;

        #pragma unroll 4
        for (int kk = 0; kk < HD; ++kk) {
            float rq[4], rk[4];
            #pragma unroll
            for (int i = 0; i < 4; ++i) rq[i] = Qs[(ty * 4 + i) * PADW + kk];
            #pragma unroll
            for (int j = 0; j < 4; ++j) rk[j] = Ks[(tx * 4 + j) * PADW + kk];
            #pragma unroll
            for (int i = 0; i < 4; ++i)
                #pragma unroll
                for (int j = 0; j < 4; ++j)
                    s[i][j] = fmaf(rq[i], rk[j], s[i][j]);
        }

        // scale + causal mask (only the diagonal tile needs masking)
        #pragma unroll
        for (int i = 0; i < 4; ++i)
            #pragma unroll
            for (int j = 0; j < 4; ++j) s[i][j] *= 0.125f;   // 1/sqrt(64)
        if (jt == it) {
            #pragma unroll
            for (int i = 0; i < 4; ++i)
                #pragma unroll
                for (int j = 0; j < 4; ++j)
                    if ((tx * 4 + j) > (ty * 4 + i)) s[i][j] = -1e30f;
        }

        // online softmax per row (row group = 16 consecutive lanes)
        #pragma unroll
        for (int i = 0; i < 4; ++i) {
            float mx = s[i][0];
            mx = fmaxf(mx, s[i][1]); mx = fmaxf(mx, s[i][2]); mx = fmaxf(mx, s[i][3]);
            #pragma unroll
            for (int o = 8; o >= 1; o >>= 1)
                mx = fmaxf(mx, __shfl_xor_sync(0xffffffffu, mx, o));
            const float mnew = fmaxf(m_i[i], mx);
            const float corr = __expf(m_i[i] - mnew);   // 0 when m_i = -inf
            m_i[i] = mnew;
            float rs = 0.f;
            #pragma unroll
            for (int j = 0; j < 4; ++j) {
                s[i][j] = __expf(s[i][j] - mnew);
                rs += s[i][j];
            }
            #pragma unroll
            for (int o = 8; o >= 1; o >>= 1)
                rs += __shfl_xor_sync(0xffffffffu, rs, o);
            l_i[i] = l_i[i] * corr + rs;
            #pragma unroll
            for (int j = 0; j < 4; ++j) {
                acc[i][j] *= corr;
                Ps[(ty * 4 + i) * PADW + tx * 4 + j] = s[i][j];
            }
        }
        __syncthreads();

        // O += P V
        #pragma unroll 4
        for (int k = 0; k < BC; ++k) {
            float rv[4];
            #pragma unroll
            for (int j = 0; j < 4; ++j) rv[j] = Vs[k * PADW + tx * 4 + j];
            #pragma unroll
            for (int i = 0; i < 4; ++i) {
                const float p = Ps[(ty * 4 + i) * PADW + k];
                #pragma unroll
                for (int j = 0; j < 4; ++j)
                    acc[i][j] = fmaf(p, rv[j], acc[i][j]);
            }
        }
    }

    // epilogue: O / l, write [b,n,dim] with head offset so Wo GEMM reads directly
    float* Ob = O + (size_t)b * N_ * DIM + h * HD;
    #pragma unroll
    for (int i = 0; i < 4; ++i) {
        const float inv = 1.f / l_i[i];
        const int r = i0 + ty * 4 + i;
        float4 v = make_float4(acc[i][0] * inv, acc[i][1] * inv,
                               acc[i][2] * inv, acc[i][3] * inv);
        *(float4*)(&Ob[(size_t)r * DIM + tx * 4]) = v;
    }
}

// ---------------------------------------------------------------------------
// kernel_launch: 5 launches, single default stream, graph-capturable.
// ---------------------------------------------------------------------------
extern "C" void kernel_launch(void* const* d_in, const int* in_sizes, int n_in,
                              void* d_out, int out_size)
{
    const float* x  = (const float*)d_in[0];
    const float* Wq = (const float*)d_in[1];
    const float* Wk = (const float*)d_in[2];
    const float* Wv = (const float*)d_in[3];
    const float* Wo = (const float*)d_in[4];
    float* out = (float*)d_out;

    float *Q, *K, *V, *O;
    cudaGetSymbolAddress((void**)&Q, g_Q);
    cudaGetSymbolAddress((void**)&K, g_K);
    cudaGetSymbolAddress((void**)&V, g_V);
    cudaGetSymbolAddress((void**)&O, g_O);

    const dim3 gemm_grid(DIM / 128, MN / 128);   // (8, 32)

    sgemm_nt<<<gemm_grid, 256>>>(x, Wq, Q, MN, DIM, DIM);
    sgemm_nt<<<gemm_grid, 256>>>(x, Wk, K, MN, DIM, DIM);
    sgemm_nt<<<gemm_grid, 256>>>(x, Wv, V, MN, DIM, DIM);

    cudaFuncSetAttribute(flash_causal,
                         cudaFuncAttributeMaxDynamicSharedMemorySize,
                         (int)FLASH_SMEM);
    flash_causal<<<dim3(N_ / BR, B_ * H_), 256, FLASH_SMEM>>>(Q, K, V, O);

    sgemm_nt<<<gemm_grid, 256>>>(O, Wo, out, MN, DIM, DIM);
}

// round 4
// speedup vs baseline: 1.5329x; 1.5329x over previous
#include <cuda_runtime.h>
#include <cuda_bf16.h>
#include <cstdint>
#include <math.h>

// Problem constants
#define B_   2
#define N_   2048
#define DIM  1024
#define H_   16
#define HD   64
#define MN   (B_ * N_)   // 4096

// ---------------------------------------------------------------------------
// Scratch (device globals)
// ---------------------------------------------------------------------------
__device__ float g_Q[(size_t)MN * DIM];
__device__ float g_K[(size_t)MN * DIM];
__device__ float g_V[(size_t)MN * DIM];
__device__ float g_O[(size_t)MN * DIM];
__device__ __nv_bfloat16 g_xh[(size_t)MN * DIM];
__device__ __nv_bfloat16 g_xl[(size_t)MN * DIM];
__device__ __nv_bfloat16 g_oh[(size_t)MN * DIM];
__device__ __nv_bfloat16 g_ol[(size_t)MN * DIM];
__device__ __nv_bfloat16 g_wh[4][(size_t)DIM * DIM];
__device__ __nv_bfloat16 g_wl[4][(size_t)DIM * DIM];

// ---------------------------------------------------------------------------
// mma.sync / ldmatrix helpers (sm_80+ PTX — legal at compute_103)
// ---------------------------------------------------------------------------
__device__ __forceinline__ uint32_t smem_u32(const void* p) {
    uint32_t a;
    asm("{ .reg .u64 t; cvta.to.shared.u64 t, %1; cvt.u32.u64 %0, t; }"
        : "=r"(a) : "l"(p));
    return a;
}

#define LDSM_X4(r0, r1, r2, r3, addr) \
    asm volatile("ldmatrix.sync.aligned.m8n8.x4.shared.b16 {%0,%1,%2,%3}, [%4];" \
                 : "=r"(r0), "=r"(r1), "=r"(r2), "=r"(r3) : "r"(addr))

#define MMA16816(d, a, b) \
    asm volatile("mma.sync.aligned.m16n8k16.row.col.f32.bf16.bf16.f32 " \
                 "{%0,%1,%2,%3}, {%4,%5,%6,%7}, {%8,%9}, {%0,%1,%2,%3};" \
                 : "+f"((d)[0]), "+f"((d)[1]), "+f"((d)[2]), "+f"((d)[3]) \
                 : "r"((a)[0]), "r"((a)[1]), "r"((a)[2]), "r"((a)[3]), \
                   "r"((b)[0]), "r"((b)[1]))

// ---------------------------------------------------------------------------
// split fp32 -> (bf16 hi, bf16 lo)
// ---------------------------------------------------------------------------
__global__ __launch_bounds__(256) void split_bf16(
    const float* __restrict__ in, __nv_bfloat16* __restrict__ hi,
    __nv_bfloat16* __restrict__ lo, int n)
{
    int i = (blockIdx.x * 256 + threadIdx.x) * 4;
    if (i >= n) return;
    float4 v = *(const float4*)(in + i);
    __nv_bfloat16 h0 = __float2bfloat16(v.x);
    __nv_bfloat16 h1 = __float2bfloat16(v.y);
    __nv_bfloat16 h2 = __float2bfloat16(v.z);
    __nv_bfloat16 h3 = __float2bfloat16(v.w);
    __nv_bfloat16 l0 = __float2bfloat16(v.x - __bfloat162float(h0));
    __nv_bfloat16 l1 = __float2bfloat16(v.y - __bfloat162float(h1));
    __nv_bfloat16 l2 = __float2bfloat16(v.z - __bfloat162float(h2));
    __nv_bfloat16 l3 = __float2bfloat16(v.w - __bfloat162float(h3));
    __nv_bfloat162* hp = (__nv_bfloat162*)(hi + i);
    __nv_bfloat162* lp = (__nv_bfloat162*)(lo + i);
    hp[0] = __nv_bfloat162(h0, h1); hp[1] = __nv_bfloat162(h2, h3);
    lp[0] = __nv_bfloat162(l0, l1); lp[1] = __nv_bfloat162(l2, l3);
}

// ---------------------------------------------------------------------------
// mma.sync GEMM:  C[4096,1024] = (Ah+Al) @ (Bh+Bl)^T,  3-term split-bf16.
// CTA tile 128x128x32, 8 warps (4m x 2n), warp tile 32x64.
// Software pipeline: prefetch next k-chunk into regs during compute.
// ---------------------------------------------------------------------------
#define BK    32
#define SPAD  40              // smem row stride in halves (80B)
#define NKCH  (DIM / BK)      // 32

__global__ __launch_bounds__(256, 1) void gemm_mma3(
    const __nv_bfloat16* __restrict__ Ah, const __nv_bfloat16* __restrict__ Al,
    const __nv_bfloat16* __restrict__ Bh, const __nv_bfloat16* __restrict__ Bl,
    float* __restrict__ C)
{
    __shared__ __nv_bfloat16 sAh[128 * SPAD], sAl[128 * SPAD];
    __shared__ __nv_bfloat16 sBh[128 * SPAD], sBl[128 * SPAD];

    const int tid  = threadIdx.x;
    const int wid  = tid >> 5;
    const int lane = tid & 31;
    const int m0 = blockIdx.y * 128;
    const int n0 = blockIdx.x * 128;
    const int wm = (wid & 3) * 32;     // warp m offset in tile
    const int wn = (wid >> 2) * 64;    // warp n offset in tile

    // global-load mapping: 512 uint4 per matrix per chunk; thread does rows r0, r0+64
    const int r0 = tid >> 2;           // 0..63
    const int c0 = (tid & 3) * 8;      // half offset within 32-wide chunk
    const __nv_bfloat16* pAh = Ah + (size_t)(m0 + r0) * DIM + c0;
    const __nv_bfloat16* pAl = Al + (size_t)(m0 + r0) * DIM + c0;
    const __nv_bfloat16* pBh = Bh + (size_t)(n0 + r0) * DIM + c0;
    const __nv_bfloat16* pBl = Bl + (size_t)(n0 + r0) * DIM + c0;
    const size_t ROWOFF = (size_t)64 * DIM;

    // smem store targets
    __nv_bfloat16* qAh0 = sAh + r0 * SPAD + c0;
    __nv_bfloat16* qAh1 = sAh + (r0 + 64) * SPAD + c0;
    __nv_bfloat16* qAl0 = sAl + r0 * SPAD + c0;
    __nv_bfloat16* qAl1 = sAl + (r0 + 64) * SPAD + c0;
    __nv_bfloat16* qBh0 = sBh + r0 * SPAD + c0;
    __nv_bfloat16* qBh1 = sBh + (r0 + 64) * SPAD + c0;
    __nv_bfloat16* qBl0 = sBl + r0 * SPAD + c0;
    __nv_bfloat16* qBl1 = sBl + (r0 + 64) * SPAD + c0;

    // ldmatrix base addresses
    const uint32_t uAh = smem_u32(sAh), uAl = smem_u32(sAl);
    const uint32_t uBh = smem_u32(sBh), uBl = smem_u32(sBl);
    const uint32_t arow = wm + (lane & 15);
    const uint32_t brow = wn + (lane & 15);
    const uint32_t koff = (lane >> 4) * 8;

    float acc[2][8][4];
    #pragma unroll
    for (int i = 0; i < 2; ++i)
        #pragma unroll
        for (int j = 0; j < 8; ++j)
            #pragma unroll
            for (int t = 0; t < 4; ++t) acc[i][j][t] = 0.f;

    uint4 fa0, fa1, fb0, fb1, fc0, fc1, fd0, fd1;
    fa0 = *(const uint4*)(pAh);          fa1 = *(const uint4*)(pAh + ROWOFF);
    fb0 = *(const uint4*)(pAl);          fb1 = *(const uint4*)(pAl + ROWOFF);
    fc0 = *(const uint4*)(pBh);          fc1 = *(const uint4*)(pBh + ROWOFF);
    fd0 = *(const uint4*)(pBl);          fd1 = *(const uint4*)(pBl + ROWOFF);

    for (int kc = 0; kc < NKCH; ++kc) {
        *(uint4*)qAh0 = fa0; *(uint4*)qAh1 = fa1;
        *(uint4*)qAl0 = fb0; *(uint4*)qAl1 = fb1;
        *(uint4*)qBh0 = fc0; *(uint4*)qBh1 = fc1;
        *(uint4*)qBl0 = fd0; *(uint4*)qBl1 = fd1;
        __syncthreads();

        if (kc + 1 < NKCH) {
            const int g = (kc + 1) * BK;
            fa0 = *(const uint4*)(pAh + g);          fa1 = *(const uint4*)(pAh + ROWOFF + g);
            fb0 = *(const uint4*)(pAl + g);          fb1 = *(const uint4*)(pAl + ROWOFF + g);
            fc0 = *(const uint4*)(pBh + g);          fc1 = *(const uint4*)(pBh + ROWOFF + g);
            fd0 = *(const uint4*)(pBl + g);          fd1 = *(const uint4*)(pBl + ROWOFF + g);
        }

        #pragma unroll
        for (int ks = 0; ks < 2; ++ks) {
            const uint32_t kbyte = (ks * 16 + koff) * 2;
            uint32_t ah[2][4], al[2][4], bh[8][2], bl[8][2];
            #pragma unroll
            for (int mt = 0; mt < 2; ++mt) {
                const uint32_t ra = (arow + mt * 16) * (SPAD * 2) + kbyte;
                LDSM_X4(ah[mt][0], ah[mt][1], ah[mt][2], ah[mt][3], uAh + ra);
                LDSM_X4(al[mt][0], al[mt][1], al[mt][2], al[mt][3], uAl + ra);
            }
            #pragma unroll
            for (int np = 0; np < 4; ++np) {
                const uint32_t rb = (brow + np * 16) * (SPAD * 2) + kbyte;
                uint32_t t0, t1, t2, t3;
                LDSM_X4(t0, t1, t2, t3, uBh + rb);
                bh[2 * np][0] = t0; bh[2 * np + 1][0] = t1;
                bh[2 * np][1] = t2; bh[2 * np + 1][1] = t3;
                LDSM_X4(t0, t1, t2, t3, uBl + rb);
                bl[2 * np][0] = t0; bl[2 * np + 1][0] = t1;
                bl[2 * np][1] = t2; bl[2 * np + 1][1] = t3;
            }
            #pragma unroll
            for (int mt = 0; mt < 2; ++mt)
                #pragma unroll
                for (int nt = 0; nt < 8; ++nt) {
                    MMA16816(acc[mt][nt], ah[mt], bh[nt]);
                    MMA16816(acc[mt][nt], ah[mt], bl[nt]);
                    MMA16816(acc[mt][nt], al[mt], bh[nt]);
                }
        }
        __syncthreads();
    }

    // epilogue: lane l holds d[m = l/4 (+8)][n = 2*(l%4)+{0,1}] per tile
    const int em = m0 + wm + (lane >> 2);
    const int en = n0 + wn + (lane & 3) * 2;
    #pragma unroll
    for (int mt = 0; mt < 2; ++mt)
        #pragma unroll
        for (int nt = 0; nt < 8; ++nt) {
            float* p0 = C + (size_t)(em + mt * 16) * DIM + en + nt * 8;
            float* p1 = p0 + 8 * DIM;
            *(float2*)p0 = make_float2(acc[mt][nt][0], acc[mt][nt][1]);
            *(float2*)p1 = make_float2(acc[mt][nt][2], acc[mt][nt][3]);
        }
}

// ---------------------------------------------------------------------------
// Causal flash attention, fp32 (unchanged)
// ---------------------------------------------------------------------------
#define BR   64
#define BC   64
#define PADW 65
#define FLASH_SMEM ((size_t)(4 * BR * PADW) * sizeof(float))

__global__ __launch_bounds__(256) void flash_causal(
    const float* __restrict__ Q, const float* __restrict__ K,
    const float* __restrict__ V, float* __restrict__ O)
{
    extern __shared__ float sm[];
    float* Qs = sm;
    float* Ks = Qs + BR * PADW;
    float* Vs = Ks + BC * PADW;
    float* Ps = Vs + BC * PADW;

    const int it  = blockIdx.x;
    const int bh  = blockIdx.y;
    const int b   = bh >> 4;
    const int h   = bh & 15;
    const int tid = threadIdx.x;
    const int tx  = tid & 15;
    const int ty  = tid >> 4;
    const int i0  = it * BR;

    const float* Qb = Q + (size_t)b * N_ * DIM + h * HD;
    const float* Kb = K + (size_t)b * N_ * DIM + h * HD;
    const float* Vb = V + (size_t)b * N_ * DIM + h * HD;

    for (int idx = tid; idx < BR * HD; idx += 256) {
        int r = idx >> 6, c = idx & 63;
        Qs[r * PADW + c] = Qb[(size_t)(i0 + r) * DIM + c];
    }

    float m_i[4], l_i[4], acc[4][4];
    #pragma unroll
    for (int i = 0; i < 4; ++i) {
        m_i[i] = -INFINITY; l_i[i] = 0.f;
        #pragma unroll
        for (int j = 0; j < 4; ++j) acc[i][j] = 0.f;
    }

    for (int jt = 0; jt <= it; ++jt) {
        const int j0 = jt * BC;
        __syncthreads();
        for (int idx = tid; idx < BC * HD; idx += 256) {
            int r = idx >> 6, c = idx & 63;
            Ks[r * PADW + c] = Kb[(size_t)(j0 + r) * DIM + c];
            Vs[r * PADW + c] = Vb[(size_t)(j0 + r) * DIM + c];
        }
        __syncthreads();

        float s[4][4];
        #pragma unroll
        for (int i = 0; i < 4; ++i)
            #pragma unroll
            for (int j = 0; j < 4; ++j) s[i][j] = 0.f;

        #pragma unroll 4
        for (int kk = 0; kk < HD; ++kk) {
            float rq[4], rk[4];
            #pragma unroll
            for (int i = 0; i < 4; ++i) rq[i] = Qs[(ty * 4 + i) * PADW + kk];
            #pragma unroll
            for (int j = 0; j < 4; ++j) rk[j] = Ks[(tx * 4 + j) * PADW + kk];
            #pragma unroll
            for (int i = 0; i < 4; ++i)
                #pragma unroll
                for (int j = 0; j < 4; ++j)
                    s[i][j] = fmaf(rq[i], rk[j], s[i][j]);
        }

        #pragma unroll
        for (int i = 0; i < 4; ++i)
            #pragma unroll
            for (int j = 0; j < 4; ++j) s[i][j] *= 0.125f;
        if (jt == it) {
            #pragma unroll
            for (int i = 0; i < 4; ++i)
                #pragma unroll
                for (int j = 0; j < 4; ++j)
                    if ((tx * 4 + j) > (ty * 4 + i)) s[i][j] = -1e30f;
        }

        #pragma unroll
        for (int i = 0; i < 4; ++i) {
            float mx = s[i][0];
            mx = fmaxf(mx, s[i][1]); mx = fmaxf(mx, s[i][2]); mx = fmaxf(mx, s[i][3]);
            #pragma unroll
            for (int o = 8; o >= 1; o >>= 1)
                mx = fmaxf(mx, __shfl_xor_sync(0xffffffffu, mx, o));
            const float mnew = fmaxf(m_i[i], mx);
            const float corr = __expf(m_i[i] - mnew);
            m_i[i] = mnew;
            float rs = 0.f;
            #pragma unroll
            for (int j = 0; j < 4; ++j) {
                s[i][j] = __expf(s[i][j] - mnew);
                rs += s[i][j];
            }
            #pragma unroll
            for (int o = 8; o >= 1; o >>= 1)
                rs += __shfl_xor_sync(0xffffffffu, rs, o);
            l_i[i] = l_i[i] * corr + rs;
            #pragma unroll
            for (int j = 0; j < 4; ++j) {
                acc[i][j] *= corr;
                Ps[(ty * 4 + i) * PADW + tx * 4 + j] = s[i][j];
            }
        }
        __syncthreads();

        #pragma unroll 4
        for (int k = 0; k < BC; ++k) {
            float rv[4];
            #pragma unroll
            for (int j = 0; j < 4; ++j) rv[j] = Vs[k * PADW + tx * 4 + j];
            #pragma unroll
            for (int i = 0; i < 4; ++i) {
                const float p = Ps[(ty * 4 + i) * PADW + k];
                #pragma unroll
                for (int j = 0; j < 4; ++j)
                    acc[i][j] = fmaf(p, rv[j], acc[i][j]);
            }
        }
    }

    float* Ob = O + (size_t)b * N_ * DIM + h * HD;
    #pragma unroll
    for (int i = 0; i < 4; ++i) {
        const float inv = 1.f / l_i[i];
        const int r = i0 + ty * 4 + i;
        float4 v = make_float4(acc[i][0] * inv, acc[i][1] * inv,
                               acc[i][2] * inv, acc[i][3] * inv);
        *(float4*)(&Ob[(size_t)r * DIM + tx * 4]) = v;
    }
}

// ---------------------------------------------------------------------------
// kernel_launch
// ---------------------------------------------------------------------------
extern "C" void kernel_launch(void* const* d_in, const int* in_sizes, int n_in,
                              void* d_out, int out_size)
{
    const float* x  = (const float*)d_in[0];
    const float* W[4] = { (const float*)d_in[1], (const float*)d_in[2],
                          (const float*)d_in[3], (const float*)d_in[4] };
    float* out = (float*)d_out;

    float *Q, *K, *V, *O;
    __nv_bfloat16 *xh, *xl, *oh, *ol, *wh[4], *wl[4];
    cudaGetSymbolAddress((void**)&Q, g_Q);
    cudaGetSymbolAddress((void**)&K, g_K);
    cudaGetSymbolAddress((void**)&V, g_V);
    cudaGetSymbolAddress((void**)&O, g_O);
    cudaGetSymbolAddress((void**)&xh, g_xh);
    cudaGetSymbolAddress((void**)&xl, g_xl);
    cudaGetSymbolAddress((void**)&oh, g_oh);
    cudaGetSymbolAddress((void**)&ol, g_ol);
    {
        char* p;
        cudaGetSymbolAddress((void**)&p, g_wh);
        for (int i = 0; i < 4; ++i) wh[i] = (__nv_bfloat16*)(p + (size_t)i * DIM * DIM * 2);
        cudaGetSymbolAddress((void**)&p, g_wl);
        for (int i = 0; i < 4; ++i) wl[i] = (__nv_bfloat16*)(p + (size_t)i * DIM * DIM * 2);
    }

    static bool attr_done = false;
    if (!attr_done) {
        cudaFuncSetAttribute(flash_causal,
            cudaFuncAttributeMaxDynamicSharedMemorySize, (int)FLASH_SMEM);
        attr_done = true;
    }

    const int nx = MN * DIM;
    const int nw = DIM * DIM;
    split_bf16<<<nx / 1024, 256>>>(x, xh, xl, nx);
    for (int i = 0; i < 4; ++i)
        split_bf16<<<nw / 1024, 256>>>(W[i], wh[i], wl[i], nw);

    const dim3 gg(DIM / 128, MN / 128);   // (8, 32)
    gemm_mma3<<<gg, 256>>>(xh, xl, wh[0], wl[0], Q);
    gemm_mma3<<<gg, 256>>>(xh, xl, wh[1], wl[1], K);
    gemm_mma3<<<gg, 256>>>(xh, xl, wh[2], wl[2], V);

    flash_causal<<<dim3(N_ / BR, B_ * H_), 256, FLASH_SMEM>>>(Q, K, V, O);

    split_bf16<<<nx / 1024, 256>>>(O, oh, ol, nx);
    gemm_mma3<<<gg, 256>>>(oh, ol, wh[3], wl[3], out);
}